// round 2
// baseline (speedup 1.0000x reference)
#include <cuda_runtime.h>

// Scratch for v1[8, 1024] — __device__ global (no allocations allowed).
__device__ float g_v1[8 * 1024];

static constexpr int B = 8;
static constexpr int T = 2048;
static constexpr int C = 1024;

// One block per output feature d. 256 threads, each owns one float4 of W[d,:].
// Computes v1[b][d] = dot(x[b,1,:], W[d,:]) + bias[d] for all 8 batches.
__global__ __launch_bounds__(256, 8)
void gemv_row1_kernel(const float* __restrict__ x,
                      const float* __restrict__ W,
                      const float* __restrict__ bias) {
    const int d   = blockIdx.x;
    const int tid = threadIdx.x;

    const float4* w4 = reinterpret_cast<const float4*>(W + (size_t)d * C);
    const float4  w  = w4[tid];

    float acc[B];
#pragma unroll
    for (int b = 0; b < B; b++) {
        // x[b, 1, :] starts at offset b*T*C + C
        const float4* x4 = reinterpret_cast<const float4*>(x + (size_t)b * T * C + C);
        const float4  xv = x4[tid];
        acc[b] = w.x * xv.x + w.y * xv.y + w.z * xv.z + w.w * xv.w;
    }

    // Warp-level reduce each of the 8 accumulators.
#pragma unroll
    for (int b = 0; b < B; b++) {
#pragma unroll
        for (int off = 16; off > 0; off >>= 1)
            acc[b] += __shfl_down_sync(0xffffffffu, acc[b], off);
    }

    __shared__ float sred[8][B];  // [warp][batch]
    const int warp = tid >> 5;
    const int lane = tid & 31;
    if (lane == 0) {
#pragma unroll
        for (int b = 0; b < B; b++) sred[warp][b] = acc[b];
    }
    __syncthreads();

    if (tid < B) {
        float s = 0.0f;
#pragma unroll
        for (int wdx = 0; wdx < 8; wdx++) s += sred[wdx][tid];
        g_v1[tid * C + d] = s + bias[d];
    }
}

// Broadcast v1[b, :] across all T rows. Pure coalesced float4 stores.
// Total float4 elements: B*T*C/4 = 4,194,304. One store per thread.
__global__ __launch_bounds__(256)
void broadcast_kernel(float4* __restrict__ out) {
    const int idx = blockIdx.x * blockDim.x + threadIdx.x;
    // per batch: T*C/4 = 2048*256 = 524288 = 2^19 float4
    const int b  = idx >> 19;
    const int d4 = idx & 255;  // C/4 = 256
    const float4* v4 = reinterpret_cast<const float4*>(g_v1);
    out[idx] = v4[(b << 8) + d4];
}

extern "C" void kernel_launch(void* const* d_in, const int* in_sizes, int n_in,
                              void* d_out, int out_size) {
    const float* x    = (const float*)d_in[0];
    const float* W    = (const float*)d_in[1];
    const float* bias = (const float*)d_in[2];
    float* out = (float*)d_out;

    gemv_row1_kernel<<<C, 256>>>(x, W, bias);

    const int total4 = B * T * C / 4;           // 4,194,304
    broadcast_kernel<<<total4 / 256, 256>>>(reinterpret_cast<float4*>(out));
}

// round 3
// speedup vs baseline: 1.1347x; 1.1347x over previous
#include <cuda_runtime.h>

// Scratch for v1[8, 1024] — __device__ global (no allocations allowed).
__device__ float g_v1[8 * 1024];

static constexpr int B = 8;
static constexpr int T = 2048;
static constexpr int C = 1024;
static constexpr int RPB = 16;   // rows (t values) stored per block

// One block per output feature d. 256 threads, each owns one float4 of W[d,:].
// Computes v1[b][d] = dot(x[b,1,:], W[d,:]) + bias[d] for all 8 batches.
__global__ __launch_bounds__(256, 8)
void gemv_row1_kernel(const float* __restrict__ x,
                      const float* __restrict__ W,
                      const float* __restrict__ bias) {
    const int d   = blockIdx.x;
    const int tid = threadIdx.x;

    const float4* w4 = reinterpret_cast<const float4*>(W + (size_t)d * C);
    const float4  w  = w4[tid];

    float acc[B];
#pragma unroll
    for (int b = 0; b < B; b++) {
        // x[b, 1, :] starts at offset b*T*C + C
        const float4* x4 = reinterpret_cast<const float4*>(x + (size_t)b * T * C + C);
        const float4  xv = x4[tid];
        acc[b] = w.x * xv.x + w.y * xv.y + w.z * xv.z + w.w * xv.w;
    }

#pragma unroll
    for (int b = 0; b < B; b++) {
#pragma unroll
        for (int off = 16; off > 0; off >>= 1)
            acc[b] += __shfl_down_sync(0xffffffffu, acc[b], off);
    }

    __shared__ float sred[8][B];  // [warp][batch]
    const int warp = tid >> 5;
    const int lane = tid & 31;
    if (lane == 0) {
#pragma unroll
        for (int b = 0; b < B; b++) sred[warp][b] = acc[b];
    }
    __syncthreads();

    if (tid < B) {
        float s = 0.0f;
#pragma unroll
        for (int wdx = 0; wdx < 8; wdx++) s += sred[wdx][tid];
        g_v1[tid * C + d] = s + bias[d];
    }
}

// Broadcast v1[b, :] across T rows. Each block: one batch b, RPB rows.
// 256 threads cover one full row (C/4 = 256 float4). Each thread loads its
// float4 of v1[b] ONCE, then issues RPB independent coalesced STG.128s.
__global__ __launch_bounds__(256)
void broadcast_kernel(float4* __restrict__ out) {
    const int tid = threadIdx.x;
    const int b   = blockIdx.y;
    const int t0  = blockIdx.x * RPB;

    const float4* v4 = reinterpret_cast<const float4*>(g_v1);
    const float4  val = v4[(b << 8) + tid];   // C/4 = 256 per batch

    // out row stride = C/4 = 256 float4
    float4* p = out + (((size_t)b * T + t0) << 8) + tid;
#pragma unroll
    for (int r = 0; r < RPB; r++) {
        p[(size_t)r << 8] = val;
    }
}

extern "C" void kernel_launch(void* const* d_in, const int* in_sizes, int n_in,
                              void* d_out, int out_size) {
    const float* x    = (const float*)d_in[0];
    const float* W    = (const float*)d_in[1];
    const float* bias = (const float*)d_in[2];
    float* out = (float*)d_out;

    gemv_row1_kernel<<<C, 256>>>(x, W, bias);

    dim3 grid(T / RPB, B);   // 128 x 8 = 1024 blocks
    broadcast_kernel<<<grid, 256>>>(reinterpret_cast<float4*>(out));
}